// round 5
// baseline (speedup 1.0000x reference)
#include <cuda_runtime.h>
#include <cuda_bf16.h>

#define N_NODES 100000
#define DEG 16
#define N_EDGES (N_NODES * DEG)
#define D_FEAT 64

// Allocation-free scratch.
__device__ float g_buf0[N_NODES * D_FEAT];
__device__ float g_buf1[N_NODES * D_FEAT];
__device__ int   g_indices[N_EDGES];
__device__ int   g_is64;

// Detect whether the harness delivered indices as int64 (odd 32-bit words all
// zero, since node ids < 100000) or int32 (odd words are random indices;
// P[64 consecutive all zero] ~ 1e-320). One warp, once per call.
__global__ void detect_kernel(const int* __restrict__ raw)
{
    const int t = threadIdx.x;                       // 0..31
    int w = raw[2 * t + 1] | raw[2 * (t + 32) + 1];  // 64 odd words total
    unsigned any = __ballot_sync(0xffffffffu, w != 0);
    if (t == 0) g_is64 = (any == 0) ? 1 : 0;
}

// Normalize indices to int32.
__global__ void convert_indices_kernel(const int* __restrict__ raw)
{
    const int e = blockIdx.x * blockDim.x + threadIdx.x;
    if (e < N_EDGES) {
        g_indices[e] = g_is64 ? raw[2 * e] : raw[e];
    }
}

// One SpMM hop. Warp per node; lane owns one float2 (2 of 64 feats).
// Each gather of x[nbr] = 32 lanes x float2 = one coalesced 256B row read.
// Edges (idx,val) loaded by lanes 0..15, broadcast via shfl.
// Two-phase batches of 8: addresses -> loads -> FMAs, forcing MLP=8/warp.
__global__ __launch_bounds__(256) void spmm_hop_kernel(
    const float* __restrict__ x,
    const float* __restrict__ values,
    float* __restrict__ out)
{
    const int node = (blockIdx.x * blockDim.x + threadIdx.x) >> 5;  // warp id
    const int lane = threadIdx.x & 31;

    const int   e      = node * DEG + (lane & 15);
    const int   my_idx = g_indices[e];
    const float my_val = __ldg(&values[e]);

    const float2* __restrict__ xv = reinterpret_cast<const float2*>(x);

    float2 acc = make_float2(0.f, 0.f);

    #pragma unroll
    for (int b = 0; b < 2; b++) {
        const float2* p[8];
        float v[8];
        #pragma unroll
        for (int k = 0; k < 8; k++) {
            const int kk  = b * 8 + k;
            const int nbr = __shfl_sync(0xffffffffu, my_idx, kk);
            v[k] = __shfl_sync(0xffffffffu, my_val, kk);
            p[k] = xv + nbr * (D_FEAT / 2) + lane;
        }
        float2 g[8];
        #pragma unroll
        for (int k = 0; k < 8; k++) g[k] = __ldg(p[k]);
        #pragma unroll
        for (int k = 0; k < 8; k++) {
            acc.x = fmaf(v[k], g[k].x, acc.x);
            acc.y = fmaf(v[k], g[k].y, acc.y);
        }
    }

    reinterpret_cast<float2*>(out)[node * (D_FEAT / 2) + lane] = acc;
}

extern "C" void kernel_launch(void* const* d_in, const int* in_sizes, int n_in,
                              void* d_out, int out_size)
{
    (void)in_sizes; (void)n_in; (void)out_size;
    const float* x       = (const float*)d_in[0];
    const float* values  = (const float*)d_in[1];
    // d_in[2] = indptr (unused; degree fixed at 16)
    const int*   raw_idx = (const int*)d_in[3];   // int32 view; layout auto-detected
    float*       out     = (float*)d_out;

    float *b0, *b1;
    cudaGetSymbolAddress((void**)&b0, g_buf0);
    cudaGetSymbolAddress((void**)&b1, g_buf1);

    detect_kernel<<<1, 32>>>(raw_idx);
    convert_indices_kernel<<<(N_EDGES + 255) / 256, 256>>>(raw_idx);

    const int threads = 256;                 // 8 warps = 8 nodes / block
    const int blocks  = N_NODES / 8;         // 12500, exact

    spmm_hop_kernel<<<blocks, threads>>>(x,  values, b0);
    spmm_hop_kernel<<<blocks, threads>>>(b0, values, b1);
    spmm_hop_kernel<<<blocks, threads>>>(b1, values, out);
}

// round 10
// speedup vs baseline: 1.1306x; 1.1306x over previous
#include <cuda_runtime.h>
#include <cuda_bf16.h>

#define N_NODES 100000
#define DEG 16
#define N_EDGES (N_NODES * DEG)
#define D_FEAT 64

// Allocation-free scratch.
__device__ float g_buf0[N_NODES * D_FEAT];
__device__ float g_buf1[N_NODES * D_FEAT];
__device__ int   g_indices[N_EDGES];
__device__ int   g_is64;

// Detect int64 vs int32 index layout (odd 32-bit words all zero <=> int64,
// since node ids < 100000; P[64 random int32 words all zero] ~ 1e-320).
__global__ void detect_kernel(const int* __restrict__ raw)
{
    const int t = threadIdx.x;                       // 0..31
    int w = raw[2 * t + 1] | raw[2 * (t + 32) + 1];
    unsigned any = __ballot_sync(0xffffffffu, w != 0);
    if (t == 0) g_is64 = (any == 0) ? 1 : 0;
}

// Normalize indices to int32 (pre-scaled to float4-row offsets: idx * 16).
__global__ void convert_indices_kernel(const int* __restrict__ raw)
{
    const int e = blockIdx.x * blockDim.x + threadIdx.x;
    if (e < N_EDGES) {
        const int idx = g_is64 ? raw[2 * e] : raw[e];
        g_indices[e] = idx * (D_FEAT / 4);   // offset in float4 units
    }
}

// One SpMM hop.
// Half-warp (16 lanes) per node; lane owns one float4 chunk of the 64-float row.
// Edges staged in smem once per block (256 pairs), then read via broadcast LDS.
// Gathers issued in explicit batches of 8 LDG.128 to force MLP=8 per warp;
// __launch_bounds__(256, 4) raises the register cap to 64 so ptxas keeps the
// batch in flight (R2/R5 showed it re-rolls at the default 32-reg budget).
__global__ __launch_bounds__(256, 4) void spmm_hop_kernel(
    const float* __restrict__ x,
    const float* __restrict__ values,
    float* __restrict__ out)
{
    __shared__ int   s_off[16 * DEG];   // pre-scaled row offsets
    __shared__ float s_val[16 * DEG];

    const int tid   = threadIdx.x;
    const int node0 = blockIdx.x * 16;           // 16 nodes per block

    // Cooperative edge stage: thread t loads edge t of this block's 256 edges.
    {
        const int e = node0 * DEG + tid;
        s_off[tid] = g_indices[e];
        s_val[tid] = __ldg(&values[e]);
    }
    __syncthreads();

    const int local = tid >> 4;                  // local node 0..15
    const int chunk = tid & 15;                  // float4 chunk of the row
    const int ebase = local * DEG;

    const float4* __restrict__ xv = reinterpret_cast<const float4*>(x);

    float4 acc = make_float4(0.f, 0.f, 0.f, 0.f);

    #pragma unroll
    for (int b = 0; b < 2; b++) {
        // Phase 1: fetch 8 (offset, value) pairs via broadcast LDS.
        int   off[8];
        float val[8];
        #pragma unroll
        for (int k = 0; k < 8; k++) {
            off[k] = s_off[ebase + b * 8 + k];
            val[k] = s_val[ebase + b * 8 + k];
        }
        // Phase 2: 8 independent LDG.128 gathers in flight.
        float4 g[8];
        #pragma unroll
        for (int k = 0; k < 8; k++) g[k] = __ldg(xv + off[k] + chunk);
        // Phase 3: FMAs.
        #pragma unroll
        for (int k = 0; k < 8; k++) {
            acc.x = fmaf(val[k], g[k].x, acc.x);
            acc.y = fmaf(val[k], g[k].y, acc.y);
            acc.z = fmaf(val[k], g[k].z, acc.z);
            acc.w = fmaf(val[k], g[k].w, acc.w);
        }
    }

    reinterpret_cast<float4*>(out)[(node0 + local) * (D_FEAT / 4) + chunk] = acc;
}

extern "C" void kernel_launch(void* const* d_in, const int* in_sizes, int n_in,
                              void* d_out, int out_size)
{
    (void)in_sizes; (void)n_in; (void)out_size;
    const float* x       = (const float*)d_in[0];
    const float* values  = (const float*)d_in[1];
    // d_in[2] = indptr (unused; degree fixed at 16)
    const int*   raw_idx = (const int*)d_in[3];   // int32 view; layout auto-detected
    float*       out     = (float*)d_out;

    float *b0, *b1;
    cudaGetSymbolAddress((void**)&b0, g_buf0);
    cudaGetSymbolAddress((void**)&b1, g_buf1);

    detect_kernel<<<1, 32>>>(raw_idx);
    convert_indices_kernel<<<(N_EDGES + 255) / 256, 256>>>(raw_idx);

    const int threads = 256;                 // 16 nodes per block
    const int blocks  = N_NODES / 16;        // 6250, exact

    spmm_hop_kernel<<<blocks, threads>>>(x,  values, b0);
    spmm_hop_kernel<<<blocks, threads>>>(b0, values, b1);
    spmm_hop_kernel<<<blocks, threads>>>(b1, values, out);
}